// round 1
// baseline (speedup 1.0000x reference)
#include <cuda_runtime.h>

// YOLOv3 loss, fused. Shapes (fixed by problem):
//  pred_large  [64,3,13,13,30]  (30 = 5 + 25 classes)
//  pred_medium [64,3,26,26,30]
//  pred_small  [64,3,52,52,30]
//  targets     [2048,6]  (bi, cid, x, y, w, h)
//  out         [4] = {tot, box, obj, cls}

#define NC 25
#define CH 30
#define MAX_CELLS (64*3*(13*13 + 26*26 + 52*52))   // 681408

__constant__ float c_anc[9][2] = {
    {116.f,  90.f}, {156.f, 198.f}, {373.f, 326.f},   // grid 13
    { 30.f,  61.f}, { 62.f,  45.f}, { 59.f, 119.f},   // grid 26
    { 10.f,  13.f}, { 16.f,  30.f}, { 33.f,  23.f}};  // grid 52

__device__ int      g_winner[MAX_CELLS];
__device__ unsigned g_clsmask[MAX_CELLS];

__device__ __forceinline__ float softplusf(float x) {
    return fmaxf(x, 0.0f) + log1pf(expf(-fabsf(x)));
}
// bce_with_logits(x, t) = softplus(x) - t*x   (exact rearrangement of the reference)
__device__ __forceinline__ float bcef(float x, float t) {
    return softplusf(x) - t * x;
}

__global__ void init_kernel(int total, float* out) {
    int i = blockIdx.x * blockDim.x + threadIdx.x;
    if (i < total) { g_winner[i] = -1; g_clsmask[i] = 0u; }
    if (i < 4) out[i] = 0.0f;
}

__global__ void scatter_kernel(const float* __restrict__ tgt, int N,
                               int off1, int off2) {
    int idx = blockIdx.x * blockDim.x + threadIdx.x;
    if (idx >= 3 * N) return;
    int s = idx / N;            // scale
    int n = idx - s * N;        // target row
    const float* T = tgt + 6 * n;
    int   gridi = (s == 0) ? 13 : (s == 1) ? 26 : 52;
    float gridf = (float)gridi;
    int   off   = (s == 0) ? 0  : (s == 1) ? off1 : off2;

    int bi  = (int)T[0];
    int cid = (int)T[1];
    float txf = T[2] * gridf, tyf = T[3] * gridf;
    float twf = T[4] * gridf, thf = T[5] * gridf;
    int gx = (int)floorf(txf), gy = (int)floorf(tyf);
    if (gx < 0 || gx >= gridi || gy < 0 || gy >= gridi) return;

    // best anchor by wh-IoU (argmax keeps first on ties, matching jnp.argmax)
    float best_iou = -1.0f; int best = 0;
    #pragma unroll
    for (int a = 0; a < 3; a++) {
        float saw = c_anc[s*3 + a][0] / gridf;
        float sah = c_anc[s*3 + a][1] / gridf;
        float inter = fminf(twf, saw) * fminf(thf, sah);
        float uni   = twf * thf + saw * sah - inter;
        float iou   = inter / (uni + 1e-9f);
        if (iou > best_iou) { best_iou = iou; best = a; }
    }

    int cell = off + ((bi * 3 + best) * gridi + gy) * gridi + gx;
    // XLA CPU scatter applies updates in row order -> last target index wins
    atomicMax(&g_winner[cell], n);
    // tcls scatter indexes (cell, cid): colliding targets union their classes
    atomicOr(&g_clsmask[cell], 1u << cid);
}

__global__ void loss_kernel(const float* __restrict__ pl,
                            const float* __restrict__ pm,
                            const float* __restrict__ ps,
                            const float* __restrict__ tgt,
                            float* __restrict__ out,
                            int off1, int off2, int total) {
    int i = blockIdx.x * blockDim.x + threadIdx.x;
    float box = 0.0f, obj = 0.0f, cls = 0.0f;

    if (i < total) {
        const float* pred; float gridf; int s, local;
        if (i < off1)      { pred = pl; gridf = 13.0f; s = 0; local = i; }
        else if (i < off2) { pred = pm; gridf = 26.0f; s = 1; local = i - off1; }
        else               { pred = ps; gridf = 52.0f; s = 2; local = i - off2; }

        const float* P = pred + (long long)local * CH;
        float po = __ldg(P + 4);
        int   w  = g_winner[i];

        if (w < 0) {
            // no-object cell: LAMBDA_NOOBJ * bce(po, 0) = 0.5 * softplus(po)
            obj = 0.5f * softplusf(po);
        } else {
            // object cell: LAMBDA_OBJ * bce(po, 1) = softplus(-po)
            obj = softplusf(-po);

            const float* T = tgt + 6 * w;
            float txf = T[2] * gridf, tyf = T[3] * gridf;
            float twf = T[4] * gridf, thf = T[5] * gridf;

            float best_iou = -1.0f; float saw_b = 1.0f, sah_b = 1.0f;
            #pragma unroll
            for (int a = 0; a < 3; a++) {
                float saw = c_anc[s*3 + a][0] / gridf;
                float sah = c_anc[s*3 + a][1] / gridf;
                float inter = fminf(twf, saw) * fminf(thf, sah);
                float uni   = twf * thf + saw * sah - inter;
                float iou   = inter / (uni + 1e-9f);
                if (iou > best_iou) { best_iou = iou; saw_b = saw; sah_b = sah; }
            }

            float tx = txf - floorf(txf);
            float ty = tyf - floorf(tyf);
            float tw = logf(twf / saw_b + 1e-16f);
            float th = logf(thf / sah_b + 1e-16f);

            float px = P[0], py = P[1], pw = P[2], ph = P[3];
            float dw = pw - tw, dh = ph - th;
            box = 5.0f * (bcef(px, tx) + bcef(py, ty) + dw * dw + dh * dh);

            unsigned m = g_clsmask[i];
            #pragma unroll
            for (int c = 0; c < NC; c++) {
                float pc = P[5 + c];
                float t  = (float)((m >> c) & 1u);
                cls += softplusf(pc) - t * pc;
            }
        }
    }

    // block reduction: warp shuffle, then per-warp shared, then atomics
    #pragma unroll
    for (int o = 16; o > 0; o >>= 1) {
        box += __shfl_down_sync(0xFFFFFFFFu, box, o);
        obj += __shfl_down_sync(0xFFFFFFFFu, obj, o);
        cls += __shfl_down_sync(0xFFFFFFFFu, cls, o);
    }
    __shared__ float sb[8], so[8], sc[8];
    int lane = threadIdx.x & 31, warp = threadIdx.x >> 5;
    if (lane == 0) { sb[warp] = box; so[warp] = obj; sc[warp] = cls; }
    __syncthreads();
    if (warp == 0) {
        box = (lane < 8) ? sb[lane] : 0.0f;
        obj = (lane < 8) ? so[lane] : 0.0f;
        cls = (lane < 8) ? sc[lane] : 0.0f;
        #pragma unroll
        for (int o = 4; o > 0; o >>= 1) {
            box += __shfl_down_sync(0xFFFFFFFFu, box, o);
            obj += __shfl_down_sync(0xFFFFFFFFu, obj, o);
            cls += __shfl_down_sync(0xFFFFFFFFu, cls, o);
        }
        if (lane == 0) {
            atomicAdd(out + 0, box + obj + cls);
            atomicAdd(out + 1, box);
            atomicAdd(out + 2, obj);
            atomicAdd(out + 3, cls);
        }
    }
}

extern "C" void kernel_launch(void* const* d_in, const int* in_sizes, int n_in,
                              void* d_out, int out_size) {
    const float* pl  = (const float*)d_in[0];
    const float* pm  = (const float*)d_in[1];
    const float* ps  = (const float*)d_in[2];
    const float* tgt = (const float*)d_in[3];
    float* out = (float*)d_out;

    int B = in_sizes[0] / (3 * 13 * 13 * CH);
    int N = in_sizes[3] / 6;
    int off1  = B * 3 * 13 * 13;
    int off2  = off1 + B * 3 * 26 * 26;
    int total = off2 + B * 3 * 52 * 52;

    init_kernel<<<(total + 255) / 256, 256>>>(total, out);
    scatter_kernel<<<(3 * N + 255) / 256, 256>>>(tgt, N, off1, off2);
    loss_kernel<<<(total + 255) / 256, 256>>>(pl, pm, ps, tgt, out,
                                              off1, off2, total);
}

// round 2
// speedup vs baseline: 1.9828x; 1.9828x over previous
#include <cuda_runtime.h>

// YOLOv3 loss, 2-kernel self-cleaning formulation.
//  pred_large  [64,3,13,13,30]   pred_medium [64,3,26,26,30]
//  pred_small  [64,3,52,52,30]   targets [2048,6]   out[4]={tot,box,obj,cls}
//
// obj_loss = sum_all 0.5*softplus(po)  +  sum_winners (0.5*softplus(po) - po)
// (since LAMBDA_OBJ*bce(po,1) = softplus(-po) = softplus(po) - po)

#define NC 25
#define CH 30
#define MAX_CELLS (64*3*(13*13 + 26*26 + 52*52))   // 681408
#define MAXT (3*2048)
#define CPT 8

__constant__ float c_anc[9][2] = {
    {116.f,  90.f}, {156.f, 198.f}, {373.f, 326.f},   // grid 13
    { 30.f,  61.f}, { 62.f,  45.f}, { 59.f, 119.f},   // grid 26
    { 10.f,  13.f}, { 16.f,  30.f}, { 33.f,  23.f}};  // grid 52

// 0 = empty (matches static zero-init); main kernel atomicExch's back to 0,
// so state is clean for every graph replay without an init kernel.
__device__ int      g_winner[MAX_CELLS];
__device__ unsigned g_clsmask[MAX_CELLS];
__device__ int      g_list[MAXT];

__device__ __forceinline__ float softplusf(float x) {
    return fmaxf(x, 0.0f) + log1pf(expf(-fabsf(x)));
}
__device__ __forceinline__ float bcef(float x, float t) {   // bce_with_logits
    return softplusf(x) - t * x;
}

__global__ void scatter_kernel(const float* __restrict__ tgt, int N,
                               int off1, int off2, float* __restrict__ out) {
    int idx = blockIdx.x * blockDim.x + threadIdx.x;
    if (idx < 4) out[idx] = 0.0f;
    if (idx >= 3 * N) return;
    int s = idx / N;
    int n = idx - s * N;
    const float* T = tgt + 6 * n;
    int   gridi = (s == 0) ? 13 : (s == 1) ? 26 : 52;
    float gridf = (float)gridi;
    int   off   = (s == 0) ? 0  : (s == 1) ? off1 : off2;

    float txf = T[2] * gridf, tyf = T[3] * gridf;
    float twf = T[4] * gridf, thf = T[5] * gridf;
    int gx = (int)floorf(txf), gy = (int)floorf(tyf);

    int cell = -1;
    if (gx >= 0 && gx < gridi && gy >= 0 && gy < gridi) {
        int bi  = (int)T[0];
        int cid = (int)T[1];
        float best_iou = -1.0f; int best = 0;
        #pragma unroll
        for (int a = 0; a < 3; a++) {
            float saw = c_anc[s*3 + a][0] / gridf;
            float sah = c_anc[s*3 + a][1] / gridf;
            float inter = fminf(twf, saw) * fminf(thf, sah);
            float uni   = twf * thf + saw * sah - inter;
            float iou   = inter / (uni + 1e-9f);
            if (iou > best_iou) { best_iou = iou; best = a; }   // first-max, like argmax
        }
        cell = off + ((bi * 3 + best) * gridi + gy) * gridi + gx;
        atomicMax(&g_winner[cell], n + 1);        // last target index wins
        atomicOr(&g_clsmask[cell], 1u << cid);    // class union on collision
    }
    g_list[idx] = cell;   // every slot overwritten each call
}

__global__ void main_kernel(const float* __restrict__ pl,
                            const float* __restrict__ pm,
                            const float* __restrict__ ps,
                            const float* __restrict__ tgt,
                            float* __restrict__ out,
                            int off1, int off2, int total, int nT) {
    int gid = blockIdx.x * blockDim.x + threadIdx.x;
    int T   = gridDim.x * blockDim.x;
    float box = 0.0f, obj = 0.0f, cls = 0.0f;

    // ---- streaming obj base: 0.5*softplus(po) over all cells (8-way MLP) ----
    float v[CPT];
    #pragma unroll
    for (int k = 0; k < CPT; k++) {
        int c = gid + k * T;
        float x = -100.0f;                 // softplus(-100) == 0
        if (c < total) {
            const float* p; int local;
            if (c < off1)      { p = pl; local = c; }
            else if (c < off2) { p = pm; local = c - off1; }
            else               { p = ps; local = c - off2; }
            x = __ldg(p + (long long)local * CH + 4);
        }
        v[k] = x;
    }
    #pragma unroll
    for (int k = 0; k < CPT; k++) obj += 0.5f * softplusf(v[k]);

    // ---- winner corrections (first nT threads), self-cleaning via exchange ----
    if (gid < nT) {
        int cell = g_list[gid];
        if (cell >= 0) {
            int w = atomicExch(&g_winner[cell], 0);       // claim + clean
            if (w > 0) {
                unsigned m = atomicExch(&g_clsmask[cell], 0u);
                int n = w - 1;
                const float* p; int local; float gridf; int s;
                if (cell < off1)      { p = pl; local = cell;        gridf = 13.0f; s = 0; }
                else if (cell < off2) { p = pm; local = cell - off1; gridf = 26.0f; s = 1; }
                else                  { p = ps; local = cell - off2; gridf = 52.0f; s = 2; }
                const float* P  = p + (long long)local * CH;
                const float* Tg = tgt + 6 * n;

                float txf = Tg[2] * gridf, tyf = Tg[3] * gridf;
                float twf = Tg[4] * gridf, thf = Tg[5] * gridf;

                float best_iou = -1.0f, saw_b = 1.0f, sah_b = 1.0f;
                #pragma unroll
                for (int a = 0; a < 3; a++) {
                    float saw = c_anc[s*3 + a][0] / gridf;
                    float sah = c_anc[s*3 + a][1] / gridf;
                    float inter = fminf(twf, saw) * fminf(thf, sah);
                    float uni   = twf * thf + saw * sah - inter;
                    float iou   = inter / (uni + 1e-9f);
                    if (iou > best_iou) { best_iou = iou; saw_b = saw; sah_b = sah; }
                }
                float tx = txf - floorf(txf);
                float ty = tyf - floorf(tyf);
                float tw = logf(twf / saw_b + 1e-16f);
                float th = logf(thf / sah_b + 1e-16f);

                float px = P[0], py = P[1], pw = P[2], ph = P[3], po = P[4];
                float dw = pw - tw, dh = ph - th;
                box = 5.0f * (bcef(px, tx) + bcef(py, ty) + dw * dw + dh * dh);

                // winner obj correction: softplus(-po) - 0.5*softplus(po)
                obj += 0.5f * softplusf(po) - po;

                #pragma unroll
                for (int c = 0; c < NC; c++) {
                    float pc = P[5 + c];
                    cls += softplusf(pc) - (((m >> c) & 1u) ? pc : 0.0f);
                }
            }
        }
    }

    // ---- block reduction then 4 atomics per block ----
    #pragma unroll
    for (int o = 16; o > 0; o >>= 1) {
        box += __shfl_down_sync(0xFFFFFFFFu, box, o);
        obj += __shfl_down_sync(0xFFFFFFFFu, obj, o);
        cls += __shfl_down_sync(0xFFFFFFFFu, cls, o);
    }
    __shared__ float sb[8], so[8], sc[8];
    int lane = threadIdx.x & 31, warp = threadIdx.x >> 5;
    if (lane == 0) { sb[warp] = box; so[warp] = obj; sc[warp] = cls; }
    __syncthreads();
    if (warp == 0) {
        box = (lane < 8) ? sb[lane] : 0.0f;
        obj = (lane < 8) ? so[lane] : 0.0f;
        cls = (lane < 8) ? sc[lane] : 0.0f;
        #pragma unroll
        for (int o = 4; o > 0; o >>= 1) {
            box += __shfl_down_sync(0xFFFFFFFFu, box, o);
            obj += __shfl_down_sync(0xFFFFFFFFu, obj, o);
            cls += __shfl_down_sync(0xFFFFFFFFu, cls, o);
        }
        if (lane == 0) {
            atomicAdd(out + 0, box + obj + cls);
            atomicAdd(out + 1, box);
            atomicAdd(out + 2, obj);
            atomicAdd(out + 3, cls);
        }
    }
}

extern "C" void kernel_launch(void* const* d_in, const int* in_sizes, int n_in,
                              void* d_out, int out_size) {
    const float* pl  = (const float*)d_in[0];
    const float* pm  = (const float*)d_in[1];
    const float* ps  = (const float*)d_in[2];
    const float* tgt = (const float*)d_in[3];
    float* out = (float*)d_out;

    int B = in_sizes[0] / (3 * 13 * 13 * CH);
    int N = in_sizes[3] / 6;
    int off1  = B * 3 * 13 * 13;
    int off2  = off1 + B * 3 * 26 * 26;
    int total = off2 + B * 3 * 52 * 52;
    int nT    = 3 * N;

    scatter_kernel<<<(nT + 255) / 256, 256>>>(tgt, N, off1, off2, out);

    int threads = (total + CPT - 1) / CPT;
    int blocks  = (threads + 255) / 256;
    main_kernel<<<blocks, 256>>>(pl, pm, ps, tgt, out, off1, off2, total, nT);
}